// round 15
// baseline (speedup 1.0000x reference)
#include <cuda_runtime.h>
#include <cuda_fp16.h>
#include <cstdint>

// Problem constants
#define Bc   2
#define Lc   2048
#define Dc   512
#define Hc   16
#define DKc  32
#define Mrows (Bc * Lc)   // 4096

// 1/sqrt(32) * log2(e): folded into the Q projection epilogue
#define QSCALE 0.2550457927534106f

// Scratch: Q/K/V half (pre-rounded), X fp32, packed mask bits
__device__ __half g_Qh[Mrows * Dc];
__device__ __half g_Kh[Mrows * Dc];
__device__ __half g_Vh[Mrows * Dc];
__device__ float  g_X[Mrows * Dc];
__device__ unsigned long long g_Mbits[Bc * Lc * (Lc / 64)];

__device__ __forceinline__ uint32_t smem_u32(const void* p) {
    return (uint32_t)__cvta_generic_to_shared(p);
}
__device__ __forceinline__ uint32_t packh2(float lo, float hi) {
    __half2 h = __floats2half2_rn(lo, hi);
    return *reinterpret_cast<uint32_t*>(&h);
}
// exp2 on a packed half2 (one MUFU op for two values)
__device__ __forceinline__ uint32_t exp2_h2(uint32_t x) {
    uint32_t y;
    asm("ex2.approx.f16x2 %0, %1;" : "=r"(y) : "r"(x));
    return y;
}
// mma m16n8k16 f16 inputs, f32 accumulate (in-place)
__device__ __forceinline__ void mma_f16(float d[4], const uint32_t a[4],
                                        const uint32_t b[2]) {
    asm volatile(
        "mma.sync.aligned.m16n8k16.row.col.f32.f16.f16.f32 "
        "{%0,%1,%2,%3}, {%4,%5,%6,%7}, {%8,%9}, {%0,%1,%2,%3};"
        : "+f"(d[0]), "+f"(d[1]), "+f"(d[2]), "+f"(d[3])
        : "r"(a[0]), "r"(a[1]), "r"(a[2]), "r"(a[3]),
          "r"(b[0]), "r"(b[1]));
}
__device__ __forceinline__ void ldsm_x4(uint32_t& r0, uint32_t& r1,
                                        uint32_t& r2, uint32_t& r3, uint32_t a) {
    asm volatile("ldmatrix.sync.aligned.m8n8.x4.shared.b16 {%0,%1,%2,%3}, [%4];"
                 : "=r"(r0), "=r"(r1), "=r"(r2), "=r"(r3) : "r"(a));
}
__device__ __forceinline__ void ldsm_x4_t(uint32_t& r0, uint32_t& r1,
                                          uint32_t& r2, uint32_t& r3, uint32_t a) {
    asm volatile("ldmatrix.sync.aligned.m8n8.x4.trans.shared.b16 {%0,%1,%2,%3}, [%4];"
                 : "=r"(r0), "=r"(r1), "=r"(r2), "=r"(r3) : "r"(a));
}
__device__ __forceinline__ void cp_async16(uint32_t dst, const void* src) {
    asm volatile("cp.async.cg.shared.global [%0], [%1], 16;"
                 :: "r"(dst), "l"(src));
}
__device__ __forceinline__ void cp_commit() {
    asm volatile("cp.async.commit_group;");
}
__device__ __forceinline__ void cp_wait0() {
    asm volatile("cp.async.wait_group 0;");
}

// ---------------------------------------------------------------------------
// Mask pack helper: one uint64 word from 64 ints.
// ---------------------------------------------------------------------------
__device__ __forceinline__ void pack_mask_word(
    const int* __restrict__ mask, unsigned long long* __restrict__ bits, int idx)
{
    const int4* p = (const int4*)(mask + (size_t)idx * 64);
    unsigned long long w = 0;
#pragma unroll
    for (int i = 0; i < 16; i++) {
        int4 v = p[i];
        unsigned long long nib =
            (unsigned long long)((v.x != 0) | ((v.y != 0) << 1) |
                                 ((v.z != 0) << 2) | ((v.w != 0) << 3));
        w |= nib << (4 * i);
    }
    bits[idx] = w;
}

// ---------------------------------------------------------------------------
// fp16 tensor-core GEMM core, double-buffered smem (1 barrier per k-tile).
// Block (32*MI) x 128, BK=16, 8 warps (2m x 4n), warp tile (16*MI) x 32.
// NSPLIT=1: plain fp16 operands. NSPLIT=3: hi/lo split (~fp32 result).
// ---------------------------------------------------------------------------
template<int MI, int NSPLIT, bool HALF_OUT>
__device__ __forceinline__ void gemm_core_f16(
    const float* __restrict__ A, const float* __restrict__ W,
    const float* __restrict__ bias, void* Cout,
    float oscale, int m0, int n0)
{
    constexpr int BM = 32 * MI;
    constexpr int AL = BM / 64;

    __shared__ __align__(16) __half Ah[2][BM][24];
    __shared__ __align__(16) __half Bh[2][16][136];
    __shared__ __align__(16) __half Al[(NSPLIT == 3) ? 2 : 1]
                                      [(NSPLIT == 3) ? BM : 1][24];
    __shared__ __align__(16) __half Bl[(NSPLIT == 3) ? 2 : 1]
                                      [(NSPLIT == 3) ? 16 : 1][136];

    const int tid = threadIdx.x;
    const int w   = tid >> 5;
    const int l   = tid & 31;
    const int g   = l >> 2;
    const int t4  = l & 3;
    const int lm  = l >> 3;
    const int lr  = l & 7;
    const int wm  = (w >> 2) * (16 * MI);
    const int wn  = (w & 3) * 32;

    int ar[AL], ac[AL];
#pragma unroll
    for (int u = 0; u < AL; u++) {
        int f = tid + 256 * u;
        ar[u] = f >> 2;
        ac[u] = (f & 3) << 2;
    }
    const int wr0 = tid >> 5,          wc0 = (tid & 31) << 2;
    const int wr1 = (tid + 256) >> 5,  wc1 = ((tid + 256) & 31) << 2;

    float acc[MI][4][4];
#pragma unroll
    for (int mi = 0; mi < MI; mi++)
#pragma unroll
        for (int ni = 0; ni < 4; ni++)
#pragma unroll
            for (int i = 0; i < 4; i++) acc[mi][ni][i] = 0.f;

    const int a_row = (lm & 1) * 8 + lr;
    const int a_col = (lm >> 1) * 8;
    const int b_row = (lm & 1) * 8 + lr;
    const int b_col = (lm >> 1) * 8;

    float4 ra[AL], rb0, rb1;

    auto stage = [&](int bufi) {
#pragma unroll
        for (int u = 0; u < AL; u++) {
            float va[4] = {ra[u].x, ra[u].y, ra[u].z, ra[u].w};
            __half e0 = __float2half_rn(va[0]), e1 = __float2half_rn(va[1]);
            __half e2 = __float2half_rn(va[2]), e3 = __float2half_rn(va[3]);
            *(__half2*)&Ah[bufi][ar[u]][ac[u]]     = __halves2half2(e0, e1);
            *(__half2*)&Ah[bufi][ar[u]][ac[u] + 2] = __halves2half2(e2, e3);
            if (NSPLIT == 3) {
                *(__half2*)&Al[bufi][ar[u]][ac[u]] = __halves2half2(
                    __float2half_rn(va[0] - __half2float(e0)),
                    __float2half_rn(va[1] - __half2float(e1)));
                *(__half2*)&Al[bufi][ar[u]][ac[u] + 2] = __halves2half2(
                    __float2half_rn(va[2] - __half2float(e2)),
                    __float2half_rn(va[3] - __half2float(e3)));
            }
        }
        float vb[8] = {rb0.x, rb0.y, rb0.z, rb0.w, rb1.x, rb1.y, rb1.z, rb1.w};
        {
            __half e0 = __float2half_rn(vb[0]), e1 = __float2half_rn(vb[1]);
            __half e2 = __float2half_rn(vb[2]), e3 = __float2half_rn(vb[3]);
            __half f0 = __float2half_rn(vb[4]), f1 = __float2half_rn(vb[5]);
            __half f2 = __float2half_rn(vb[6]), f3 = __float2half_rn(vb[7]);
            *(__half2*)&Bh[bufi][wr0][wc0]     = __halves2half2(e0, e1);
            *(__half2*)&Bh[bufi][wr0][wc0 + 2] = __halves2half2(e2, e3);
            *(__half2*)&Bh[bufi][wr1][wc1]     = __halves2half2(f0, f1);
            *(__half2*)&Bh[bufi][wr1][wc1 + 2] = __halves2half2(f2, f3);
            if (NSPLIT == 3) {
                *(__half2*)&Bl[bufi][wr0][wc0] = __halves2half2(
                    __float2half_rn(vb[0] - __half2float(e0)),
                    __float2half_rn(vb[1] - __half2float(e1)));
                *(__half2*)&Bl[bufi][wr0][wc0 + 2] = __halves2half2(
                    __float2half_rn(vb[2] - __half2float(e2)),
                    __float2half_rn(vb[3] - __half2float(e3)));
                *(__half2*)&Bl[bufi][wr1][wc1] = __halves2half2(
                    __float2half_rn(vb[4] - __half2float(f0)),
                    __float2half_rn(vb[5] - __half2float(f1)));
                *(__half2*)&Bl[bufi][wr1][wc1 + 2] = __halves2half2(
                    __float2half_rn(vb[6] - __half2float(f2)),
                    __float2half_rn(vb[7] - __half2float(f3)));
            }
        }
    };
    auto loadk = [&](int kt) {
#pragma unroll
        for (int u = 0; u < AL; u++)
            ra[u] = *(const float4*)(A + (size_t)(m0 + ar[u]) * Dc + kt + ac[u]);
        rb0 = *(const float4*)(W + (size_t)(kt + wr0) * Dc + n0 + wc0);
        rb1 = *(const float4*)(W + (size_t)(kt + wr1) * Dc + n0 + wc1);
    };

    loadk(0);
    stage(0);
    __syncthreads();

    const int NIT = Dc / 16;   // 32
    for (int it = 0; it < NIT; it++) {
        const int cur  = it & 1;
        const bool more = (it + 1 < NIT);
        if (more) loadk((it + 1) * 16);

        uint32_t af[MI][4], afl[MI][4];
#pragma unroll
        for (int mi = 0; mi < MI; mi++) {
            ldsm_x4(af[mi][0], af[mi][1], af[mi][2], af[mi][3],
                    smem_u32(&Ah[cur][wm + 16 * mi + a_row][a_col]));
            if (NSPLIT == 3)
                ldsm_x4(afl[mi][0], afl[mi][1], afl[mi][2], afl[mi][3],
                        smem_u32(&Al[cur][wm + 16 * mi + a_row][a_col]));
        }
        uint32_t bf[4][2], bfl[4][2];
#pragma unroll
        for (int p = 0; p < 2; p++) {
            uint32_t r0, r1, r2, r3;
            ldsm_x4_t(r0, r1, r2, r3,
                      smem_u32(&Bh[cur][b_row][wn + p * 16 + b_col]));
            bf[p * 2][0] = r0; bf[p * 2][1] = r1;
            bf[p * 2 + 1][0] = r2; bf[p * 2 + 1][1] = r3;
            if (NSPLIT == 3) {
                ldsm_x4_t(r0, r1, r2, r3,
                          smem_u32(&Bl[cur][b_row][wn + p * 16 + b_col]));
                bfl[p * 2][0] = r0; bfl[p * 2][1] = r1;
                bfl[p * 2 + 1][0] = r2; bfl[p * 2 + 1][1] = r3;
            }
        }
#pragma unroll
        for (int mi = 0; mi < MI; mi++)
#pragma unroll
            for (int ni = 0; ni < 4; ni++) {
                if (NSPLIT == 3) {
                    mma_f16(acc[mi][ni], af[mi], bfl[ni]);
                    mma_f16(acc[mi][ni], afl[mi], bf[ni]);
                }
                mma_f16(acc[mi][ni], af[mi], bf[ni]);
            }

        if (more) stage(cur ^ 1);
        __syncthreads();
    }

    float2 bv[4];
#pragma unroll
    for (int ni = 0; ni < 4; ni++)
        bv[ni] = *(const float2*)(bias + n0 + wn + 8 * ni + 2 * t4);

#pragma unroll
    for (int mi = 0; mi < MI; mi++) {
        int row = m0 + wm + 16 * mi + g;
#pragma unroll
        for (int ni = 0; ni < 4; ni++) {
            int col = n0 + wn + 8 * ni + 2 * t4;
            float c0 = acc[mi][ni][0] + bv[ni].x;
            float c1 = acc[mi][ni][1] + bv[ni].y;
            float c2 = acc[mi][ni][2] + bv[ni].x;
            float c3 = acc[mi][ni][3] + bv[ni].y;
            if (HALF_OUT) {
                __half* hC = (__half*)Cout;
                *(uint32_t*)(hC + (size_t)row * Dc + col) =
                    packh2(c0 * oscale, c1 * oscale);
                *(uint32_t*)(hC + (size_t)(row + 8) * Dc + col) =
                    packh2(c2 * oscale, c3 * oscale);
            } else {
                float* fC = (float*)Cout;
                float2 v0 = {c0, c1};
                float2 v1 = {c2, c3};
                *(float2*)(fC + (size_t)row * Dc + col)       = v0;
                *(float2*)(fC + (size_t)(row + 8) * Dc + col) = v1;
            }
        }
    }
}

// Merged QKV projection + mask pack. Grid (4, 64, 4):
// z=0/1/2 -> Q/K/V projections (64-row blocks); z=3 -> mask bit packing
// (DRAM-bound, overlaps the tensor-bound GEMM slabs).
__global__ __launch_bounds__(256, 2) void qkv_gemm_f16(
    const float* __restrict__ q, const float* __restrict__ k,
    const float* __restrict__ v,
    const float* __restrict__ wq, const float* __restrict__ bq,
    const float* __restrict__ wk, const float* __restrict__ bk,
    const float* __restrict__ wv, const float* __restrict__ bv,
    __half* __restrict__ gQ, __half* __restrict__ gK, __half* __restrict__ gV,
    const int* __restrict__ mask, unsigned long long* __restrict__ mbits)
{
    if (blockIdx.z == 3) {
        // 256 blocks x 256 threads x 2 words = 131072 words
        int w0 = (blockIdx.y * 4 + blockIdx.x) * 256 + threadIdx.x;
        pack_mask_word(mask, mbits, w0);
        pack_mask_word(mask, mbits, w0 + 65536);
        return;
    }
    const float* A; const float* W; const float* B; __half* C; float scl;
    if (blockIdx.z == 0)      { A = q; W = wq; B = bq; C = gQ; scl = QSCALE; }
    else if (blockIdx.z == 1) { A = k; W = wk; B = bk; C = gK; scl = 1.f; }
    else                      { A = v; W = wv; B = bv; C = gV; scl = 1.f; }
    gemm_core_f16<2, 1, true>(A, W, B, C, scl, blockIdx.y * 64, blockIdx.x * 128);
}

// Output projection: 3-term fp16 split (~fp32), 64-row blocks = 256 blocks.
__global__ __launch_bounds__(256, 2) void out_gemm_f16(
    const float* __restrict__ A, const float* __restrict__ W,
    const float* __restrict__ bias, float* __restrict__ C)
{
    gemm_core_f16<2, 3, false>(A, W, bias, C, 1.f, blockIdx.y * 64, blockIdx.x * 128);
}

// ---------------------------------------------------------------------------
// fp16 flash attention, persistent blocks (296 = 2/SM, no wave tail).
// 128-key smem stages (cp.async double-buffered), processed as two 64-key
// halves; softmax exp2 on packed half2; row sums via ones-mma.
// Each of the 512 (qt,bh) units: 128 q-rows, 8 warps x 16 rows.
// ---------------------------------------------------------------------------
#define NUNITS 512
#define ABLOCKS 296

__global__ __launch_bounds__(256, 2) void attn_f16(
    const __half* __restrict__ Qp, const __half* __restrict__ Kp,
    const __half* __restrict__ Vp, const unsigned long long* __restrict__ Mb,
    float* __restrict__ Xp)
{
    __shared__ __align__(16) __half Kh[2][128][40];
    __shared__ __align__(16) __half Vh[2][128][40];

    const int tid = threadIdx.x;
    const int w   = tid >> 5;
    const int l   = tid & 31;
    const int g   = l >> 2;
    const int t4  = l & 3;
    const int lm  = l >> 3;
    const int lr  = l & 7;

    // Staging: 128 rows x 32 halfs (64B) = 512 chunks of 16B (8 halfs).
    // Chunk c -> row c>>2, col (c&3)*8. Thread handles chunks tid, tid+256.
    const int cr0 = tid >> 2;
    const int cc0 = (tid & 3) * 8;
    const int cr1 = (tid + 256) >> 2;
    const int cc1 = ((tid + 256) & 3) * 8;

    const uint32_t ones2[2] = {0x3C003C00u, 0x3C003C00u};

    for (int unit = blockIdx.x; unit < NUNITS; unit += ABLOCKS) {
        const int qt = unit & 15;
        const int bh = unit >> 4;
        const int b  = bh >> 4;
        const int h  = bh & 15;

        const int qrowA = qt * 128 + w * 16 + g;
        const int qrowB = qrowA + 8;

        // Q fragments (pre-scaled by QSCALE in projection)
        uint32_t qf[2][4];
        {
            const __half* qa = Qp + (size_t)(b * Lc + qrowA) * Dc + h * DKc;
            const __half* qb = Qp + (size_t)(b * Lc + qrowB) * Dc + h * DKc;
#pragma unroll
            for (int kb = 0; kb < 2; kb++) {
                qf[kb][0] = *(const uint32_t*)(qa + kb * 16 + 2 * t4);
                qf[kb][1] = *(const uint32_t*)(qb + kb * 16 + 2 * t4);
                qf[kb][2] = *(const uint32_t*)(qa + kb * 16 + 8 + 2 * t4);
                qf[kb][3] = *(const uint32_t*)(qb + kb * 16 + 8 + 2 * t4);
            }
        }

        float o[4][4];
#pragma unroll
        for (int n = 0; n < 4; n++)
#pragma unroll
            for (int i = 0; i < 4; i++) o[n][i] = 0.f;
        float osum[4] = {0.f, 0.f, 0.f, 0.f};

        const unsigned long long* mpA = Mb + (size_t)(b * Lc + qrowA) * (Lc / 64);
        const unsigned long long* mpB = Mb + (size_t)(b * Lc + qrowB) * (Lc / 64);

        const __half* Kg = Kp + (size_t)(b * Lc) * Dc + h * DKc;
        const __half* Vg = Vp + (size_t)(b * Lc) * Dc + h * DKc;

        // Prologue: 128-key tile 0 into buffer 0
        __syncthreads();   // prior unit's buffer reads complete before restage
        cp_async16(smem_u32(&Kh[0][cr0][cc0]), Kg + (size_t)cr0 * Dc + cc0);
        cp_async16(smem_u32(&Kh[0][cr1][cc1]), Kg + (size_t)cr1 * Dc + cc1);
        cp_async16(smem_u32(&Vh[0][cr0][cc0]), Vg + (size_t)cr0 * Dc + cc0);
        cp_async16(smem_u32(&Vh[0][cr1][cc1]), Vg + (size_t)cr1 * Dc + cc1);
        cp_commit();
        unsigned long long wAn0 = mpA[0], wAn1 = mpA[1];
        unsigned long long wBn0 = mpB[0], wBn1 = mpB[1];

        const int NIT = Lc / 128;   // 16
        for (int jt = 0; jt < NIT; jt++) {
            const int cur = jt & 1;
            cp_wait0();
            __syncthreads();
            unsigned long long wA[2] = {wAn0, wAn1};
            unsigned long long wB[2] = {wBn0, wBn1};
            if (jt + 1 < NIT) {
                const int nxt = cur ^ 1;
                size_t base = (size_t)((jt + 1) * 128);
                cp_async16(smem_u32(&Kh[nxt][cr0][cc0]), Kg + (base + cr0) * Dc + cc0);
                cp_async16(smem_u32(&Kh[nxt][cr1][cc1]), Kg + (base + cr1) * Dc + cc1);
                cp_async16(smem_u32(&Vh[nxt][cr0][cc0]), Vg + (base + cr0) * Dc + cc0);
                cp_async16(smem_u32(&Vh[nxt][cr1][cc1]), Vg + (base + cr1) * Dc + cc1);
                cp_commit();
                wAn0 = mpA[2 * jt + 2]; wAn1 = mpA[2 * jt + 3];
                wBn0 = mpB[2 * jt + 2]; wBn1 = mpB[2 * jt + 3];
            }

            // Two 64-key halves within the staged 128-key tile
#pragma unroll
            for (int hk = 0; hk < 2; hk++) {
                const int kbase = hk * 64;

                // ---- S = Q.K^T ----
                float s[8][4];
#pragma unroll
                for (int nb = 0; nb < 8; nb++)
#pragma unroll
                    for (int i = 0; i < 4; i++) s[nb][i] = 0.f;
#pragma unroll
                for (int kb = 0; kb < 2; kb++) {
#pragma unroll
                    for (int nbp = 0; nbp < 4; nbp++) {
                        uint32_t r0, r1, r2, r3;
                        ldsm_x4(r0, r1, r2, r3,
                                smem_u32(&Kh[cur][kbase + (nbp * 2 + (lm >> 1)) * 8 + lr]
                                            [kb * 16 + (lm & 1) * 8]));
                        uint32_t b0[2] = {r0, r1};
                        uint32_t b1[2] = {r2, r3};
                        mma_f16(s[nbp * 2], qf[kb], b0);
                        mma_f16(s[nbp * 2 + 1], qf[kb], b1);
                    }
                }

                // ---- mask, pack to half2, exp2 in half domain ----
                uint32_t ph[8][2];
#pragma unroll
                for (int nb = 0; nb < 8; nb++) {
                    int c0 = nb * 8 + 2 * t4;
                    float s0 = ((wA[hk] >> c0) & 1ull)       ? s[nb][0] : -3e4f;
                    float s1 = ((wA[hk] >> (c0 + 1)) & 1ull) ? s[nb][1] : -3e4f;
                    float s2 = ((wB[hk] >> c0) & 1ull)       ? s[nb][2] : -3e4f;
                    float s3 = ((wB[hk] >> (c0 + 1)) & 1ull) ? s[nb][3] : -3e4f;
                    ph[nb][0] = exp2_h2(packh2(s0, s1));
                    ph[nb][1] = exp2_h2(packh2(s2, s3));
                }

                // ---- O += P.V ; osum += P.ones ----
#pragma unroll
                for (int kbp = 0; kbp < 4; kbp++) {
                    uint32_t af[4] = {ph[2 * kbp][0], ph[2 * kbp][1],
                                      ph[2 * kbp + 1][0], ph[2 * kbp + 1][1]};
                    mma_f16(osum, af, ones2);
#pragma unroll
                    for (int np = 0; np < 2; np++) {
                        uint32_t r0, r1, r2, r3;
                        ldsm_x4_t(r0, r1, r2, r3,
                                  smem_u32(&Vh[cur][kbase + kbp * 16 + (lm & 1) * 8 + lr]
                                              [np * 16 + (lm >> 1) * 8]));
                        uint32_t b0[2] = {r0, r1};
                        uint32_t b1[2] = {r2, r3};
                        mma_f16(o[np * 2], af, b0);
                        mma_f16(o[np * 2 + 1], af, b1);
                    }
                }
            }
        }

        // osum[0] = row sum for qrowA, osum[2] for qrowB
        float invA = 1.0f / osum[0];
        float invB = 1.0f / osum[2];
#pragma unroll
        for (int n = 0; n < 4; n++) {
            int col = h * DKc + n * 8 + 2 * t4;
            float2 va = {o[n][0] * invA, o[n][1] * invA};
            float2 vb = {o[n][2] * invB, o[n][3] * invB};
            *(float2*)(Xp + (size_t)(b * Lc + qrowA) * Dc + col) = va;
            *(float2*)(Xp + (size_t)(b * Lc + qrowB) * Dc + col) = vb;
        }
    }
}

// ---------------------------------------------------------------------------
// Launch
// ---------------------------------------------------------------------------
extern "C" void kernel_launch(void* const* d_in, const int* in_sizes, int n_in,
                              void* d_out, int out_size)
{
    const float* q    = (const float*)d_in[0];
    const float* k    = (const float*)d_in[1];
    const float* v    = (const float*)d_in[2];
    const int*   mask = (const int*)  d_in[3];
    // d_in[4] = is_training (unused)
    const float* wq = (const float*)d_in[5];
    const float* bq = (const float*)d_in[6];
    const float* wk = (const float*)d_in[7];
    const float* bk = (const float*)d_in[8];
    const float* wv = (const float*)d_in[9];
    const float* bv = (const float*)d_in[10];
    const float* wo = (const float*)d_in[11];
    const float* bo = (const float*)d_in[12];
    float* out = (float*)d_out;

    __half *gQ, *gK, *gV;
    float* gX;
    unsigned long long* gM;
    cudaGetSymbolAddress((void**)&gQ, g_Qh);
    cudaGetSymbolAddress((void**)&gK, g_Kh);
    cudaGetSymbolAddress((void**)&gV, g_Vh);
    cudaGetSymbolAddress((void**)&gX, g_X);
    cudaGetSymbolAddress((void**)&gM, g_Mbits);

    // QKV projections + mask packing in one launch (z=3 slab packs mask)
    dim3 qkvgrid(Dc / 128, Mrows / 64, 4);    // (4, 64, 4) = 1024 blocks
    qkv_gemm_f16<<<qkvgrid, 256>>>(q, k, v, wq, bq, wk, bk, wv, bv,
                                   gQ, gK, gV, mask, gM);

    attn_f16<<<ABLOCKS, 256>>>(gQ, gK, gV, gM, gX);

    dim3 ogrid(Dc / 128, Mrows / 64);         // (4, 64) = 256 blocks
    out_gemm_f16<<<ogrid, 256>>>(gX, wo, bo, out);
}

// round 17
// speedup vs baseline: 1.0713x; 1.0713x over previous
#include <cuda_runtime.h>
#include <cuda_fp16.h>
#include <cstdint>

// Problem constants
#define Bc   2
#define Lc   2048
#define Dc   512
#define Hc   16
#define DKc  32
#define Mrows (Bc * Lc)   // 4096

// 1/sqrt(32) * log2(e): folded into the Q projection epilogue
#define QSCALE 0.2550457927534106f

// Scratch: Q/K/V half (pre-rounded), X fp32, packed mask bits
__device__ __half g_Qh[Mrows * Dc];
__device__ __half g_Kh[Mrows * Dc];
__device__ __half g_Vh[Mrows * Dc];
__device__ float  g_X[Mrows * Dc];
__device__ unsigned long long g_Mbits[Bc * Lc * (Lc / 64)];

__device__ __forceinline__ uint32_t smem_u32(const void* p) {
    return (uint32_t)__cvta_generic_to_shared(p);
}
__device__ __forceinline__ uint32_t packh2(float lo, float hi) {
    __half2 h = __floats2half2_rn(lo, hi);
    return *reinterpret_cast<uint32_t*>(&h);
}
// exp2 on a packed half2 (one MUFU op for two values)
__device__ __forceinline__ uint32_t exp2_h2(uint32_t x) {
    uint32_t y;
    asm("ex2.approx.f16x2 %0, %1;" : "=r"(y) : "r"(x));
    return y;
}
// mma m16n8k16 f16 inputs, f32 accumulate (in-place)
__device__ __forceinline__ void mma_f16(float d[4], const uint32_t a[4],
                                        const uint32_t b[2]) {
    asm volatile(
        "mma.sync.aligned.m16n8k16.row.col.f32.f16.f16.f32 "
        "{%0,%1,%2,%3}, {%4,%5,%6,%7}, {%8,%9}, {%0,%1,%2,%3};"
        : "+f"(d[0]), "+f"(d[1]), "+f"(d[2]), "+f"(d[3])
        : "r"(a[0]), "r"(a[1]), "r"(a[2]), "r"(a[3]),
          "r"(b[0]), "r"(b[1]));
}
__device__ __forceinline__ void ldsm_x4(uint32_t& r0, uint32_t& r1,
                                        uint32_t& r2, uint32_t& r3, uint32_t a) {
    asm volatile("ldmatrix.sync.aligned.m8n8.x4.shared.b16 {%0,%1,%2,%3}, [%4];"
                 : "=r"(r0), "=r"(r1), "=r"(r2), "=r"(r3) : "r"(a));
}
__device__ __forceinline__ void ldsm_x4_t(uint32_t& r0, uint32_t& r1,
                                          uint32_t& r2, uint32_t& r3, uint32_t a) {
    asm volatile("ldmatrix.sync.aligned.m8n8.x4.trans.shared.b16 {%0,%1,%2,%3}, [%4];"
                 : "=r"(r0), "=r"(r1), "=r"(r2), "=r"(r3) : "r"(a));
}
__device__ __forceinline__ void cp_async16(uint32_t dst, const void* src) {
    asm volatile("cp.async.cg.shared.global [%0], [%1], 16;"
                 :: "r"(dst), "l"(src));
}
__device__ __forceinline__ void cp_commit() {
    asm volatile("cp.async.commit_group;");
}
__device__ __forceinline__ void cp_wait0() {
    asm volatile("cp.async.wait_group 0;");
}

// ---------------------------------------------------------------------------
// Pre-pass: pack int mask (B,1,L,L) into uint64 bitmask. One word per thread.
// ---------------------------------------------------------------------------
__global__ __launch_bounds__(256) void mask_to_bits(
    const int* __restrict__ mask, unsigned long long* __restrict__ bits)
{
    int idx = blockIdx.x * 256 + threadIdx.x;
    const int4* p = (const int4*)(mask + (size_t)idx * 64);
    unsigned long long w = 0;
#pragma unroll
    for (int i = 0; i < 16; i++) {
        int4 v = p[i];
        unsigned long long nib =
            (unsigned long long)((v.x != 0) | ((v.y != 0) << 1) |
                                 ((v.z != 0) << 2) | ((v.w != 0) << 3));
        w |= nib << (4 * i);
    }
    bits[idx] = w;
}

// ---------------------------------------------------------------------------
// fp16 tensor-core GEMM core, double-buffered smem (1 barrier per k-tile).
// Block (32*MI) x 128, 8 warps (2m x 4n), warp tile (16*MI) x 32, m16n8k16.
// BK = k-tile depth (16 or 32; 32 halves barrier count).
// NSPLIT=1: plain fp16 operands. NSPLIT=3: hi/lo split (~fp32 result).
// ---------------------------------------------------------------------------
template<int MI, int BK, int NSPLIT, bool HALF_OUT>
__device__ __forceinline__ void gemm_core_f16(
    const float* __restrict__ A, const float* __restrict__ W,
    const float* __restrict__ bias, void* Cout,
    float oscale, int m0, int n0)
{
    constexpr int BM = 32 * MI;
    constexpr int AL = BM * BK / 1024;     // float4 A-loads per thread
    constexpr int WL = BK / 8;             // float4 B-loads per thread
    constexpr int APAD = BK + 8;

    __shared__ __align__(16) __half Ah[2][BM][APAD];
    __shared__ __align__(16) __half Bh[2][BK][136];
    __shared__ __align__(16) __half Al[(NSPLIT == 3) ? 2 : 1]
                                      [(NSPLIT == 3) ? BM : 1][APAD];
    __shared__ __align__(16) __half Bl[(NSPLIT == 3) ? 2 : 1]
                                      [(NSPLIT == 3) ? BK : 1][136];

    const int tid = threadIdx.x;
    const int w   = tid >> 5;
    const int l   = tid & 31;
    const int g   = l >> 2;
    const int t4  = l & 3;
    const int lm  = l >> 3;
    const int lr  = l & 7;
    const int wm  = (w >> 2) * (16 * MI);
    const int wn  = (w & 3) * 32;

    int ar[AL], ac[AL];
#pragma unroll
    for (int u = 0; u < AL; u++) {
        int f = tid + 256 * u;
        ar[u] = f / (BK / 4);
        ac[u] = (f % (BK / 4)) * 4;
    }
    int wr[WL], wc[WL];
#pragma unroll
    for (int u = 0; u < WL; u++) {
        int f = tid + 256 * u;
        wr[u] = f >> 5;
        wc[u] = (f & 31) << 2;
    }

    float acc[MI][4][4];
#pragma unroll
    for (int mi = 0; mi < MI; mi++)
#pragma unroll
        for (int ni = 0; ni < 4; ni++)
#pragma unroll
            for (int i = 0; i < 4; i++) acc[mi][ni][i] = 0.f;

    const int a_row = (lm & 1) * 8 + lr;
    const int a_col = (lm >> 1) * 8;
    const int b_row = (lm & 1) * 8 + lr;
    const int b_col = (lm >> 1) * 8;

    float4 ra[AL], rb[WL];

    auto stage = [&](int bufi) {
#pragma unroll
        for (int u = 0; u < AL; u++) {
            float va[4] = {ra[u].x, ra[u].y, ra[u].z, ra[u].w};
            __half e0 = __float2half_rn(va[0]), e1 = __float2half_rn(va[1]);
            __half e2 = __float2half_rn(va[2]), e3 = __float2half_rn(va[3]);
            *(__half2*)&Ah[bufi][ar[u]][ac[u]]     = __halves2half2(e0, e1);
            *(__half2*)&Ah[bufi][ar[u]][ac[u] + 2] = __halves2half2(e2, e3);
            if (NSPLIT == 3) {
                *(__half2*)&Al[bufi][ar[u]][ac[u]] = __halves2half2(
                    __float2half_rn(va[0] - __half2float(e0)),
                    __float2half_rn(va[1] - __half2float(e1)));
                *(__half2*)&Al[bufi][ar[u]][ac[u] + 2] = __halves2half2(
                    __float2half_rn(va[2] - __half2float(e2)),
                    __float2half_rn(va[3] - __half2float(e3)));
            }
        }
#pragma unroll
        for (int u = 0; u < WL; u++) {
            float vb[4] = {rb[u].x, rb[u].y, rb[u].z, rb[u].w};
            __half e0 = __float2half_rn(vb[0]), e1 = __float2half_rn(vb[1]);
            __half e2 = __float2half_rn(vb[2]), e3 = __float2half_rn(vb[3]);
            *(__half2*)&Bh[bufi][wr[u]][wc[u]]     = __halves2half2(e0, e1);
            *(__half2*)&Bh[bufi][wr[u]][wc[u] + 2] = __halves2half2(e2, e3);
            if (NSPLIT == 3) {
                *(__half2*)&Bl[bufi][wr[u]][wc[u]] = __halves2half2(
                    __float2half_rn(vb[0] - __half2float(e0)),
                    __float2half_rn(vb[1] - __half2float(e1)));
                *(__half2*)&Bl[bufi][wr[u]][wc[u] + 2] = __halves2half2(
                    __float2half_rn(vb[2] - __half2float(e2)),
                    __float2half_rn(vb[3] - __half2float(e3)));
            }
        }
    };
    auto loadk = [&](int kt) {
#pragma unroll
        for (int u = 0; u < AL; u++)
            ra[u] = *(const float4*)(A + (size_t)(m0 + ar[u]) * Dc + kt + ac[u]);
#pragma unroll
        for (int u = 0; u < WL; u++)
            rb[u] = *(const float4*)(W + (size_t)(kt + wr[u]) * Dc + n0 + wc[u]);
    };

    loadk(0);
    stage(0);
    __syncthreads();

    const int NIT = Dc / BK;
    for (int it = 0; it < NIT; it++) {
        const int cur  = it & 1;
        const bool more = (it + 1 < NIT);
        if (more) loadk((it + 1) * BK);

#pragma unroll
        for (int kc = 0; kc < BK / 16; kc++) {
            uint32_t af[MI][4], afl[MI][4];
#pragma unroll
            for (int mi = 0; mi < MI; mi++) {
                ldsm_x4(af[mi][0], af[mi][1], af[mi][2], af[mi][3],
                        smem_u32(&Ah[cur][wm + 16 * mi + a_row][kc * 16 + a_col]));
                if (NSPLIT == 3)
                    ldsm_x4(afl[mi][0], afl[mi][1], afl[mi][2], afl[mi][3],
                            smem_u32(&Al[cur][wm + 16 * mi + a_row][kc * 16 + a_col]));
            }
            uint32_t bf[4][2], bfl[4][2];
#pragma unroll
            for (int p = 0; p < 2; p++) {
                uint32_t r0, r1, r2, r3;
                ldsm_x4_t(r0, r1, r2, r3,
                          smem_u32(&Bh[cur][kc * 16 + b_row][wn + p * 16 + b_col]));
                bf[p * 2][0] = r0; bf[p * 2][1] = r1;
                bf[p * 2 + 1][0] = r2; bf[p * 2 + 1][1] = r3;
                if (NSPLIT == 3) {
                    ldsm_x4_t(r0, r1, r2, r3,
                              smem_u32(&Bl[cur][kc * 16 + b_row][wn + p * 16 + b_col]));
                    bfl[p * 2][0] = r0; bfl[p * 2][1] = r1;
                    bfl[p * 2 + 1][0] = r2; bfl[p * 2 + 1][1] = r3;
                }
            }
#pragma unroll
            for (int mi = 0; mi < MI; mi++)
#pragma unroll
                for (int ni = 0; ni < 4; ni++) {
                    if (NSPLIT == 3) {
                        mma_f16(acc[mi][ni], af[mi], bfl[ni]);
                        mma_f16(acc[mi][ni], afl[mi], bf[ni]);
                    }
                    mma_f16(acc[mi][ni], af[mi], bf[ni]);
                }
        }

        if (more) stage(cur ^ 1);
        __syncthreads();
    }

    float2 bv[4];
#pragma unroll
    for (int ni = 0; ni < 4; ni++)
        bv[ni] = *(const float2*)(bias + n0 + wn + 8 * ni + 2 * t4);

#pragma unroll
    for (int mi = 0; mi < MI; mi++) {
        int row = m0 + wm + 16 * mi + g;
#pragma unroll
        for (int ni = 0; ni < 4; ni++) {
            int col = n0 + wn + 8 * ni + 2 * t4;
            float c0 = acc[mi][ni][0] + bv[ni].x;
            float c1 = acc[mi][ni][1] + bv[ni].y;
            float c2 = acc[mi][ni][2] + bv[ni].x;
            float c3 = acc[mi][ni][3] + bv[ni].y;
            if (HALF_OUT) {
                __half* hC = (__half*)Cout;
                *(uint32_t*)(hC + (size_t)row * Dc + col) =
                    packh2(c0 * oscale, c1 * oscale);
                *(uint32_t*)(hC + (size_t)(row + 8) * Dc + col) =
                    packh2(c2 * oscale, c3 * oscale);
            } else {
                float* fC = (float*)Cout;
                float2 v0 = {c0, c1};
                float2 v1 = {c2, c3};
                *(float2*)(fC + (size_t)row * Dc + col)       = v0;
                *(float2*)(fC + (size_t)(row + 8) * Dc + col) = v1;
            }
        }
    }
}

// Merged QKV projection (half out; Q pre-scaled by QSCALE). 768 blocks. BK=32.
__global__ __launch_bounds__(256, 2) void qkv_gemm_f16(
    const float* __restrict__ q, const float* __restrict__ k,
    const float* __restrict__ v,
    const float* __restrict__ wq, const float* __restrict__ bq,
    const float* __restrict__ wk, const float* __restrict__ bk,
    const float* __restrict__ wv, const float* __restrict__ bv,
    __half* __restrict__ gQ, __half* __restrict__ gK, __half* __restrict__ gV)
{
    const float* A; const float* W; const float* B; __half* C; float scl;
    if (blockIdx.z == 0)      { A = q; W = wq; B = bq; C = gQ; scl = QSCALE; }
    else if (blockIdx.z == 1) { A = k; W = wk; B = bk; C = gK; scl = 1.f; }
    else                      { A = v; W = wv; B = bv; C = gV; scl = 1.f; }
    gemm_core_f16<2, 32, 1, true>(A, W, B, C, scl, blockIdx.y * 64, blockIdx.x * 128);
}

// Output projection: 3-term fp16 split (~fp32), BK=16, 256 blocks.
__global__ __launch_bounds__(256, 2) void out_gemm_f16(
    const float* __restrict__ A, const float* __restrict__ W,
    const float* __restrict__ bias, float* __restrict__ C)
{
    gemm_core_f16<2, 16, 3, false>(A, W, bias, C, 1.f, blockIdx.y * 64, blockIdx.x * 128);
}

// ---------------------------------------------------------------------------
// fp16 flash attention, persistent blocks (296 = 2/SM, no wave tail).
// 128-key smem stages (cp.async double-buffered), processed as two 64-key
// halves; softmax exp2 on packed half2; row sums via ones-mma.
// (unchanged from R15 — measured ~85us)
// ---------------------------------------------------------------------------
#define NUNITS 512
#define ABLOCKS 296

__global__ __launch_bounds__(256, 2) void attn_f16(
    const __half* __restrict__ Qp, const __half* __restrict__ Kp,
    const __half* __restrict__ Vp, const unsigned long long* __restrict__ Mb,
    float* __restrict__ Xp)
{
    __shared__ __align__(16) __half Kh[2][128][40];
    __shared__ __align__(16) __half Vh[2][128][40];

    const int tid = threadIdx.x;
    const int w   = tid >> 5;
    const int l   = tid & 31;
    const int g   = l >> 2;
    const int t4  = l & 3;
    const int lm  = l >> 3;
    const int lr  = l & 7;

    // Staging: 128 rows x 32 halfs (64B) = 512 chunks of 16B (8 halfs).
    // Chunk c -> row c>>2, col (c&3)*8. Thread handles chunks tid, tid+256.
    const int cr0 = tid >> 2;
    const int cc0 = (tid & 3) * 8;
    const int cr1 = (tid + 256) >> 2;
    const int cc1 = ((tid + 256) & 3) * 8;

    const uint32_t ones2[2] = {0x3C003C00u, 0x3C003C00u};

    for (int unit = blockIdx.x; unit < NUNITS; unit += ABLOCKS) {
        const int qt = unit & 15;
        const int bh = unit >> 4;
        const int b  = bh >> 4;
        const int h  = bh & 15;

        const int qrowA = qt * 128 + w * 16 + g;
        const int qrowB = qrowA + 8;

        // Q fragments (pre-scaled by QSCALE in projection)
        uint32_t qf[2][4];
        {
            const __half* qa = Qp + (size_t)(b * Lc + qrowA) * Dc + h * DKc;
            const __half* qb = Qp + (size_t)(b * Lc + qrowB) * Dc + h * DKc;
#pragma unroll
            for (int kb = 0; kb < 2; kb++) {
                qf[kb][0] = *(const uint32_t*)(qa + kb * 16 + 2 * t4);
                qf[kb][1] = *(const uint32_t*)(qb + kb * 16 + 2 * t4);
                qf[kb][2] = *(const uint32_t*)(qa + kb * 16 + 8 + 2 * t4);
                qf[kb][3] = *(const uint32_t*)(qb + kb * 16 + 8 + 2 * t4);
            }
        }

        float o[4][4];
#pragma unroll
        for (int n = 0; n < 4; n++)
#pragma unroll
            for (int i = 0; i < 4; i++) o[n][i] = 0.f;
        float osum[4] = {0.f, 0.f, 0.f, 0.f};

        const unsigned long long* mpA = Mb + (size_t)(b * Lc + qrowA) * (Lc / 64);
        const unsigned long long* mpB = Mb + (size_t)(b * Lc + qrowB) * (Lc / 64);

        const __half* Kg = Kp + (size_t)(b * Lc) * Dc + h * DKc;
        const __half* Vg = Vp + (size_t)(b * Lc) * Dc + h * DKc;

        // Prologue: 128-key tile 0 into buffer 0
        __syncthreads();   // prior unit's buffer reads complete before restage
        cp_async16(smem_u32(&Kh[0][cr0][cc0]), Kg + (size_t)cr0 * Dc + cc0);
        cp_async16(smem_u32(&Kh[0][cr1][cc1]), Kg + (size_t)cr1 * Dc + cc1);
        cp_async16(smem_u32(&Vh[0][cr0][cc0]), Vg + (size_t)cr0 * Dc + cc0);
        cp_async16(smem_u32(&Vh[0][cr1][cc1]), Vg + (size_t)cr1 * Dc + cc1);
        cp_commit();
        unsigned long long wAn0 = mpA[0], wAn1 = mpA[1];
        unsigned long long wBn0 = mpB[0], wBn1 = mpB[1];

        const int NIT = Lc / 128;   // 16
        for (int jt = 0; jt < NIT; jt++) {
            const int cur = jt & 1;
            cp_wait0();
            __syncthreads();
            unsigned long long wA[2] = {wAn0, wAn1};
            unsigned long long wB[2] = {wBn0, wBn1};
            if (jt + 1 < NIT) {
                const int nxt = cur ^ 1;
                size_t base = (size_t)((jt + 1) * 128);
                cp_async16(smem_u32(&Kh[nxt][cr0][cc0]), Kg + (base + cr0) * Dc + cc0);
                cp_async16(smem_u32(&Kh[nxt][cr1][cc1]), Kg + (base + cr1) * Dc + cc1);
                cp_async16(smem_u32(&Vh[nxt][cr0][cc0]), Vg + (base + cr0) * Dc + cc0);
                cp_async16(smem_u32(&Vh[nxt][cr1][cc1]), Vg + (base + cr1) * Dc + cc1);
                cp_commit();
                wAn0 = mpA[2 * jt + 2]; wAn1 = mpA[2 * jt + 3];
                wBn0 = mpB[2 * jt + 2]; wBn1 = mpB[2 * jt + 3];
            }

            // Two 64-key halves within the staged 128-key tile
#pragma unroll
            for (int hk = 0; hk < 2; hk++) {
                const int kbase = hk * 64;

                // ---- S = Q.K^T ----
                float s[8][4];
#pragma unroll
                for (int nb = 0; nb < 8; nb++)
#pragma unroll
                    for (int i = 0; i < 4; i++) s[nb][i] = 0.f;
#pragma unroll
                for (int kb = 0; kb < 2; kb++) {
#pragma unroll
                    for (int nbp = 0; nbp < 4; nbp++) {
                        uint32_t r0, r1, r2, r3;
                        ldsm_x4(r0, r1, r2, r3,
                                smem_u32(&Kh[cur][kbase + (nbp * 2 + (lm >> 1)) * 8 + lr]
                                            [kb * 16 + (lm & 1) * 8]));
                        uint32_t b0[2] = {r0, r1};
                        uint32_t b1[2] = {r2, r3};
                        mma_f16(s[nbp * 2], qf[kb], b0);
                        mma_f16(s[nbp * 2 + 1], qf[kb], b1);
                    }
                }

                // ---- mask, pack to half2, exp2 in half domain ----
                uint32_t ph[8][2];
#pragma unroll
                for (int nb = 0; nb < 8; nb++) {
                    int c0 = nb * 8 + 2 * t4;
                    float s0 = ((wA[hk] >> c0) & 1ull)       ? s[nb][0] : -3e4f;
                    float s1 = ((wA[hk] >> (c0 + 1)) & 1ull) ? s[nb][1] : -3e4f;
                    float s2 = ((wB[hk] >> c0) & 1ull)       ? s[nb][2] : -3e4f;
                    float s3 = ((wB[hk] >> (c0 + 1)) & 1ull) ? s[nb][3] : -3e4f;
                    ph[nb][0] = exp2_h2(packh2(s0, s1));
                    ph[nb][1] = exp2_h2(packh2(s2, s3));
                }

                // ---- O += P.V ; osum += P.ones ----
#pragma unroll
                for (int kbp = 0; kbp < 4; kbp++) {
                    uint32_t af[4] = {ph[2 * kbp][0], ph[2 * kbp][1],
                                      ph[2 * kbp + 1][0], ph[2 * kbp + 1][1]};
                    mma_f16(osum, af, ones2);
#pragma unroll
                    for (int np = 0; np < 2; np++) {
                        uint32_t r0, r1, r2, r3;
                        ldsm_x4_t(r0, r1, r2, r3,
                                  smem_u32(&Vh[cur][kbase + kbp * 16 + (lm & 1) * 8 + lr]
                                              [np * 16 + (lm >> 1) * 8]));
                        uint32_t b0[2] = {r0, r1};
                        uint32_t b1[2] = {r2, r3};
                        mma_f16(o[np * 2], af, b0);
                        mma_f16(o[np * 2 + 1], af, b1);
                    }
                }
            }
        }

        // osum[0] = row sum for qrowA, osum[2] for qrowB
        float invA = 1.0f / osum[0];
        float invB = 1.0f / osum[2];
#pragma unroll
        for (int n = 0; n < 4; n++) {
            int col = h * DKc + n * 8 + 2 * t4;
            float2 va = {o[n][0] * invA, o[n][1] * invA};
            float2 vb = {o[n][2] * invB, o[n][3] * invB};
            *(float2*)(Xp + (size_t)(b * Lc + qrowA) * Dc + col) = va;
            *(float2*)(Xp + (size_t)(b * Lc + qrowB) * Dc + col) = vb;
        }
    }
}

// ---------------------------------------------------------------------------
// Launch
// ---------------------------------------------------------------------------
extern "C" void kernel_launch(void* const* d_in, const int* in_sizes, int n_in,
                              void* d_out, int out_size)
{
    const float* q    = (const float*)d_in[0];
    const float* k    = (const float*)d_in[1];
    const float* v    = (const float*)d_in[2];
    const int*   mask = (const int*)  d_in[3];
    // d_in[4] = is_training (unused)
    const float* wq = (const float*)d_in[5];
    const float* bq = (const float*)d_in[6];
    const float* wk = (const float*)d_in[7];
    const float* bk = (const float*)d_in[8];
    const float* wv = (const float*)d_in[9];
    const float* bv = (const float*)d_in[10];
    const float* wo = (const float*)d_in[11];
    const float* bo = (const float*)d_in[12];
    float* out = (float*)d_out;

    __half *gQ, *gK, *gV;
    float* gX;
    unsigned long long* gM;
    cudaGetSymbolAddress((void**)&gQ, g_Qh);
    cudaGetSymbolAddress((void**)&gK, g_Kh);
    cudaGetSymbolAddress((void**)&gV, g_Vh);
    cudaGetSymbolAddress((void**)&gX, g_X);
    cudaGetSymbolAddress((void**)&gM, g_Mbits);

    int nwords = Bc * Lc * (Lc / 64);
    mask_to_bits<<<nwords / 256, 256>>>(mask, gM);

    dim3 qkvgrid(Dc / 128, Mrows / 64, 3);    // (4, 64, 3) = 768 blocks
    qkv_gemm_f16<<<qkvgrid, 256>>>(q, k, v, wq, bq, wk, bk, wv, bv, gQ, gK, gV);

    attn_f16<<<ABLOCKS, 256>>>(gQ, gK, gV, gM, gX);

    dim3 ogrid(Dc / 128, Mrows / 64);         // (4, 64) = 256 blocks
    out_gemm_f16<<<ogrid, 256>>>(gX, wo, bo, out);
}